// round 10
// baseline (speedup 1.0000x reference)
#include <cuda_runtime.h>

#define B_TOT   8192
#define T_IN    1024
#define T_OUT   1088               // 1024 + 64 free-running
#define EPB     32                 // elements per block
#define THREADS 128                // 4 warps; lane = le*4 + sub (8 elems/warp)
#define CHUNK   32
#define NCHUNK  (T_OUT / CHUNK)    // 34
#define XST     33                 // xbuf/ybuf row stride (float)

typedef unsigned long long ull;

__device__ __forceinline__ ull pk2(float lo, float hi) {
    ull r; asm("mov.b64 %0, {%1, %2};" : "=l"(r) : "f"(lo), "f"(hi)); return r;
}
__device__ __forceinline__ ull ffma2(ull a, ull b, ull c) {
    ull d; asm("fma.rn.f32x2 %0, %1, %2, %3;" : "=l"(d) : "l"(a), "l"(b), "l"(c)); return d;
}
__device__ __forceinline__ float2 unpk(ull v) {
    float lo, hi; asm("mov.b64 {%0, %1}, %2;" : "=f"(lo), "=f"(hi) : "l"(v));
    return make_float2(lo, hi);
}
__device__ __forceinline__ float tanh_fast(float x) {
    float y; asm("tanh.approx.f32 %0, %1;" : "=f"(y) : "f"(x)); return y;
}
__device__ __forceinline__ float sigf(float x) {
    return fmaf(tanh_fast(0.5f * x), 0.5f, 0.5f);
}

// one packed pair-row dot: 6 LDS.128; the 4 subs' slots are adjacent (stride 4
// ulonglong2 per jj step) -> warp touches 64 contiguous bytes -> 1 wavefront.
__device__ __forceinline__ void dotq(const ulonglong2* __restrict__ p,
                                     const ull* hh, ull& a) {
    #pragma unroll
    for (int jj = 0; jj < 6; jj++) {
        ulonglong2 v = p[jj * 4];
        a = ffma2(hh[2 * jj],     v.x, a);
        a = ffma2(hh[2 * jj + 1], v.y, a);
    }
}

__global__ __launch_bounds__(THREADS)
void lstm_seq_kernel(const float* __restrict__ input,
                     const float* __restrict__ w_ih1, const float* __restrict__ w_hh1,
                     const float* __restrict__ b_ih1, const float* __restrict__ b_hh1,
                     const float* __restrict__ w_ih2, const float* __restrict__ w_hh2,
                     const float* __restrict__ b_ih2, const float* __restrict__ b_hh2,
                     const float* __restrict__ w_lin, const float* __restrict__ b_lin,
                     float* __restrict__ out)
{
    // sub-contiguous gate-packed weights (ull idx within a matrix):
    //   idx = pos*8 + sub*2 + t,  pos = (m*2+pair)*6 + jj,  j = 2*jj+t,
    //   u = sub*3 + m;  pair0=(i,f): rA=u, rB=12+u;  pair1=(g,o): rA=24+u, rB=36+u
    //   value = pk2(W[rA*12+j], W[rB*12+j])
    __shared__ alignas(16) ull s_pk1[288], s_pki2[288], s_pkh2[288];
    __shared__ alignas(16) float xbuf[CHUNK * XST];
    __shared__ alignas(16) float ybuf[CHUNK * XST];

    const int tid  = threadIdx.x;
    const int lane = tid & 31;
    const int le   = tid >> 2;      // block-local element 0..31
    const int sub  = tid & 3;       // unit group: owns units sub*3..sub*3+2
    const int u0   = sub * 3;

    // ---- stage packed weights ----
    for (int idx = tid; idx < 288; idx += THREADS) {
        const int t   = idx & 1;
        const int sb  = (idx >> 1) & 3;
        const int pos = idx >> 3;
        const int jj  = pos % 6;
        const int pp  = (pos / 6) & 1;
        const int m   = pos / 12;
        const int u   = sb * 3 + m;
        const int j   = 2 * jj + t;
        const int rA  = (pp ? 24 : 0) + u;
        const int rB  = (pp ? 36 : 12) + u;
        s_pk1[idx]  = pk2(w_hh1[rA * 12 + j], w_hh1[rB * 12 + j]);
        s_pki2[idx] = pk2(w_ih2[rA * 12 + j], w_ih2[rB * 12 + j]);
        s_pkh2[idx] = pk2(w_hh2[rA * 12 + j], w_hh2[rB * 12 + j]);
    }

    // per-thread packed constants (3 owned units)
    ull wx_if[3], wx_go[3], bz1_if[3], bz1_go[3], bz2_if[3], bz2_go[3];
    float wl[3];
    #pragma unroll
    for (int m = 0; m < 3; m++) {
        const int u = u0 + m;
        wx_if[m]  = pk2(w_ih1[u],      w_ih1[12 + u]);
        wx_go[m]  = pk2(w_ih1[24 + u], w_ih1[36 + u]);
        bz1_if[m] = pk2(b_ih1[u] + b_hh1[u],           b_ih1[12 + u] + b_hh1[12 + u]);
        bz1_go[m] = pk2(b_ih1[24 + u] + b_hh1[24 + u], b_ih1[36 + u] + b_hh1[36 + u]);
        bz2_if[m] = pk2(b_ih2[u] + b_hh2[u],           b_ih2[12 + u] + b_hh2[12 + u]);
        bz2_go[m] = pk2(b_ih2[24 + u] + b_hh2[24 + u], b_ih2[36 + u] + b_hh2[36 + u]);
        wl[m] = w_lin[u];
    }
    const float blin = b_lin[0];

    // state: h replicated as (h,h) packs, c private to owned units
    ull hh1[12], hh2[12];
    float c1[3], c2[3];
    #pragma unroll
    for (int j = 0; j < 12; j++) { hh1[j] = 0ULL; hh2[j] = 0ULL; }
    #pragma unroll
    for (int m = 0; m < 3; m++) { c1[m] = 0.0f; c2[m] = 0.0f; }

    const size_t eg0 = (size_t)blockIdx.x * EPB;

    const ulonglong2* p1 = (const ulonglong2*)s_pk1;
    const ulonglong2* pi2 = (const ulonglong2*)s_pki2;
    const ulonglong2* ph2 = (const ulonglong2*)s_pkh2;

    for (int ck = 0; ck < NCHUNK; ck++) {
        const int tbase = ck * CHUNK;

        // ---- stage x chunk: threads 0..63, 2 per element, 16 steps each ----
        if (tid < 64) {
            const int e    = tid & 31;
            const int half = tid >> 5;
            const float* src = input + (eg0 + e) * T_IN;
            if (tbase < T_IN) {
                const float4* p = (const float4*)(src + tbase + half * 16);
                #pragma unroll
                for (int q = 0; q < 4; q++) {
                    float4 v = p[q];
                    const int t0 = half * 16 + q * 4;
                    xbuf[(t0 + 0) * XST + e] = v.x;
                    xbuf[(t0 + 1) * XST + e] = v.y;
                    xbuf[(t0 + 2) * XST + e] = v.z;
                    xbuf[(t0 + 3) * XST + e] = v.w;
                }
            } else {
                const float xl = src[T_IN - 1];   // free-running: repeat last input
                #pragma unroll
                for (int k = 0; k < 16; k++)
                    xbuf[(half * 16 + k) * XST + e] = xl;
            }
        }
        __syncthreads();

        #pragma unroll 1
        for (int i = 0; i < CHUNK; i++) {
            const float x = xbuf[i * XST + le];
            const ull xx = pk2(x, x);

            // ---------- layer 1 (3 owned units) ----------
            float h1n[3];
            #pragma unroll
            for (int m = 0; m < 3; m++) {
                ull aif = ffma2(xx, wx_if[m], bz1_if[m]);
                ull ago = ffma2(xx, wx_go[m], bz1_go[m]);
                dotq(p1 + (m * 2 + 0) * 24 + sub, hh1, aif);
                dotq(p1 + (m * 2 + 1) * 24 + sub, hh1, ago);
                float2 gif = unpk(aif), ggo = unpk(ago);
                float cc = fmaf(sigf(gif.y), c1[m], sigf(gif.x) * tanh_fast(ggo.x));
                c1[m] = cc;
                h1n[m] = sigf(ggo.y) * tanh_fast(cc);
            }
            // quad all-gather h1 (width-4 shuffles, no barrier)
            #pragma unroll
            for (int s = 0; s < 4; s++) {
                float a = __shfl_sync(0xffffffffu, h1n[0], s, 4);
                float b = __shfl_sync(0xffffffffu, h1n[1], s, 4);
                float c = __shfl_sync(0xffffffffu, h1n[2], s, 4);
                hh1[s * 3 + 0] = pk2(a, a);
                hh1[s * 3 + 1] = pk2(b, b);
                hh1[s * 3 + 2] = pk2(c, c);
            }

            // ---------- layer 2 ----------
            float h2n[3];
            #pragma unroll
            for (int m = 0; m < 3; m++) {
                ull aif = bz2_if[m];
                ull ago = bz2_go[m];
                dotq(pi2 + (m * 2 + 0) * 24 + sub, hh1, aif);
                dotq(pi2 + (m * 2 + 1) * 24 + sub, hh1, ago);
                dotq(ph2 + (m * 2 + 0) * 24 + sub, hh2, aif);
                dotq(ph2 + (m * 2 + 1) * 24 + sub, hh2, ago);
                float2 gif = unpk(aif), ggo = unpk(ago);
                float cc = fmaf(sigf(gif.y), c2[m], sigf(gif.x) * tanh_fast(ggo.x));
                c2[m] = cc;
                h2n[m] = sigf(ggo.y) * tanh_fast(cc);
            }
            // quad all-gather h2
            #pragma unroll
            for (int s = 0; s < 4; s++) {
                float a = __shfl_sync(0xffffffffu, h2n[0], s, 4);
                float b = __shfl_sync(0xffffffffu, h2n[1], s, 4);
                float c = __shfl_sync(0xffffffffu, h2n[2], s, 4);
                hh2[s * 3 + 0] = pk2(a, a);
                hh2[s * 3 + 1] = pk2(b, b);
                hh2[s * 3 + 2] = pk2(c, c);
            }

            // ---------- linear head + quad reduce ----------
            float yp = h2n[0] * wl[0] + h2n[1] * wl[1] + h2n[2] * wl[2];
            yp += __shfl_xor_sync(0xffffffffu, yp, 1, 4);
            yp += __shfl_xor_sync(0xffffffffu, yp, 2, 4);
            if (sub == 0) ybuf[i * XST + le] = yp + blin;
        }
        __syncthreads();   // ybuf complete across warps

        // ---- drain y chunk to gmem (float4 stores) ----
        if (tid < 64) {
            const int e = tid & 31, half = tid >> 5;
            #pragma unroll
            for (int q = 0; q < 4; q++) {
                const int t0 = half * 16 + q * 4;
                float4 v;
                v.x = ybuf[(t0 + 0) * XST + e];
                v.y = ybuf[(t0 + 1) * XST + e];
                v.z = ybuf[(t0 + 2) * XST + e];
                v.w = ybuf[(t0 + 3) * XST + e];
                *(float4*)(out + (eg0 + e) * T_OUT + tbase + t0) = v;
            }
        }
    }
}

extern "C" void kernel_launch(void* const* d_in, const int* in_sizes, int n_in,
                              void* d_out, int out_size) {
    // metadata order: input, future(int scalar), w_ih1, w_hh1, b_ih1, b_hh1,
    //                 w_ih2, w_hh2, b_ih2, b_hh2, w_lin, b_lin
    int base = (n_in >= 12 && in_sizes[1] == 1) ? 2 : 1;  // skip 'future' scalar if present
    const float* input = (const float*)d_in[0];
    const float* w_ih1 = (const float*)d_in[base + 0];
    const float* w_hh1 = (const float*)d_in[base + 1];
    const float* b_ih1 = (const float*)d_in[base + 2];
    const float* b_hh1 = (const float*)d_in[base + 3];
    const float* w_ih2 = (const float*)d_in[base + 4];
    const float* w_hh2 = (const float*)d_in[base + 5];
    const float* b_ih2 = (const float*)d_in[base + 6];
    const float* b_hh2 = (const float*)d_in[base + 7];
    const float* w_lin = (const float*)d_in[base + 8];
    const float* b_lin = (const float*)d_in[base + 9];

    lstm_seq_kernel<<<B_TOT / EPB, THREADS>>>(
        input, w_ih1, w_hh1, b_ih1, b_hh1,
        w_ih2, w_hh2, b_ih2, b_hh2, w_lin, b_lin,
        (float*)d_out);
}

// round 11
// speedup vs baseline: 1.2076x; 1.2076x over previous
#include <cuda_runtime.h>

#define B_TOT   8192
#define T_IN    1024
#define T_OUT   1088               // 1024 + 64 free-running
#define EPB     16                 // elements per block
#define THREADS 96                 // 3 warps; lane<16: g=2w, lane>=16: g=2w+1; e=lane&15
#define CHUNK   32
#define NCHUNK  (T_OUT / CHUNK)    // 34
#define XST     17                 // xbuf/ybuf row stride (float), odd
#define HST     14                 // h-exchange row stride (ull): 7 float4 -> conflict-free

typedef unsigned long long ull;

__device__ __forceinline__ ull pk2(float lo, float hi) {
    ull r; asm("mov.b64 %0, {%1, %2};" : "=l"(r) : "f"(lo), "f"(hi)); return r;
}
__device__ __forceinline__ ull ffma2(ull a, ull b, ull c) {
    ull d; asm("fma.rn.f32x2 %0, %1, %2, %3;" : "=l"(d) : "l"(a), "l"(b), "l"(c)); return d;
}
__device__ __forceinline__ ull add2(ull a, ull b) {
    ull d; asm("add.rn.f32x2 %0, %1, %2;" : "=l"(d) : "l"(a), "l"(b)); return d;
}
__device__ __forceinline__ float2 unpk(ull v) {
    float lo, hi; asm("mov.b64 {%0, %1}, %2;" : "=f"(lo), "=f"(hi) : "l"(v));
    return make_float2(lo, hi);
}
__device__ __forceinline__ float tanh_fast(float x) {
    float y; asm("tanh.approx.f32 %0, %1;" : "=f"(y) : "f"(x)); return y;
}
__device__ __forceinline__ float sigf(float x) {
    return fmaf(tanh_fast(0.5f * x), 0.5f, 0.5f);
}

// pair-row dot: 6 broadcast LDS.128 (the warp's two g-slots are adjacent 16B
// blocks -> 32B span -> 1 wavefront), 12 FFMA2 into one accumulator.
__device__ __forceinline__ void dot1(const ulonglong2* __restrict__ p,
                                     const ull* hh, ull& a) {
    #pragma unroll
    for (int jj = 0; jj < 6; jj++) {
        ulonglong2 v = p[jj * 6];
        a = ffma2(hh[2 * jj],     v.x, a);
        a = ffma2(hh[2 * jj + 1], v.y, a);
    }
}

__global__ __launch_bounds__(THREADS, 4)
void lstm_seq_kernel(const float* __restrict__ input,
                     const float* __restrict__ w_ih1, const float* __restrict__ w_hh1,
                     const float* __restrict__ b_ih1, const float* __restrict__ b_hh1,
                     const float* __restrict__ w_ih2, const float* __restrict__ w_hh2,
                     const float* __restrict__ b_ih2, const float* __restrict__ b_hh2,
                     const float* __restrict__ w_lin, const float* __restrict__ b_lin,
                     float* __restrict__ out)
{
    // group-minor gate-packed weights (layout verified in R8):
    // flat ull idx = (pos*6 + g)*2 + t, pos = (m*2+pair)*6 + jj, j = 2*jj+t,
    // u = 2g+m; pair0=(i,f): rA=u, rB=12+u; pair1=(g,o): rA=24+u, rB=36+u;
    // value = pk2(W[rA*12+j], W[rB*12+j])
    __shared__ alignas(16) ull s_pk1[288], s_pki2[288], s_pkh2[288];
    __shared__ alignas(16) ull s_wl[12];            // pk2(wl_j, wl_j)
    __shared__ alignas(16) float xbuf[CHUNK * XST];
    __shared__ alignas(16) float ybuf[CHUNK * XST];
    __shared__ alignas(16) ull h1buf[EPB * HST];    // pre-packed (h,h) per [e][j]
    __shared__ alignas(16) ull h2buf[EPB * HST];

    const int tid  = threadIdx.x;
    const int wid  = tid >> 5;
    const int lane = tid & 31;
    const int g    = 2 * wid + (lane >> 4);   // unit-group 0..5 (units 2g, 2g+1)
    const int e    = lane & 15;               // owned element

    // ---- stage packed weights (group-minor) ----
    for (int idx = tid; idx < 288; idx += THREADS) {
        int pos = idx / 12, rem = idx % 12, gg = rem >> 1, t = rem & 1;
        int m = pos / 12, rem2 = pos % 12, pair = rem2 / 6, jj = rem2 % 6;
        int j = jj * 2 + t;
        int u = 2 * gg + m;
        int rA = (pair ? 24 : 0) + u;
        int rB = (pair ? 36 : 12) + u;
        s_pk1[idx]  = pk2(w_hh1[rA * 12 + j], w_hh1[rB * 12 + j]);
        s_pki2[idx] = pk2(w_ih2[rA * 12 + j], w_ih2[rB * 12 + j]);
        s_pkh2[idx] = pk2(w_hh2[rA * 12 + j], w_hh2[rB * 12 + j]);
    }
    if (tid < 12) s_wl[tid] = pk2(w_lin[tid], w_lin[tid]);

    // per-thread packed constants (2 owned units)
    ull wx_if[2], wx_go[2], bz1_if[2], bz1_go[2], bz2_if[2], bz2_go[2];
    #pragma unroll
    for (int m = 0; m < 2; m++) {
        const int u = 2 * g + m;
        wx_if[m]  = pk2(w_ih1[u],      w_ih1[12 + u]);
        wx_go[m]  = pk2(w_ih1[24 + u], w_ih1[36 + u]);
        bz1_if[m] = pk2(b_ih1[u] + b_hh1[u],           b_ih1[12 + u] + b_hh1[12 + u]);
        bz1_go[m] = pk2(b_ih1[24 + u] + b_hh1[24 + u], b_ih1[36 + u] + b_hh1[36 + u]);
        bz2_if[m] = pk2(b_ih2[u] + b_hh2[u],           b_ih2[12 + u] + b_hh2[12 + u]);
        bz2_go[m] = pk2(b_ih2[24 + u] + b_hh2[24 + u], b_ih2[36 + u] + b_hh2[36 + u]);
    }
    const float blin = b_lin[0];

    // state: h replicated as (h,h) packs, c private to owned units
    ull hh1[12], hh2[12];
    float c1[2], c2[2];
    #pragma unroll
    for (int j = 0; j < 12; j++) { hh1[j] = 0ULL; hh2[j] = 0ULL; }
    #pragma unroll
    for (int m = 0; m < 2; m++) { c1[m] = 0.0f; c2[m] = 0.0f; }

    const size_t eg0 = (size_t)blockIdx.x * EPB;

    const ulonglong2* p1  = (const ulonglong2*)s_pk1;
    const ulonglong2* pi2 = (const ulonglong2*)s_pki2;
    const ulonglong2* ph2 = (const ulonglong2*)s_pkh2;

    for (int ck = 0; ck < NCHUNK; ck++) {
        const int tbase = ck * CHUNK;

        // ---- stage x chunk: threads 0..31, 2 per element, 16 steps each ----
        if (tid < 32) {
            const int ee   = tid & 15;
            const int half = tid >> 4;
            const float* src = input + (eg0 + ee) * T_IN;
            if (tbase < T_IN) {
                const float4* p = (const float4*)(src + tbase + half * 16);
                #pragma unroll
                for (int q = 0; q < 4; q++) {
                    float4 v = p[q];
                    const int t0 = half * 16 + q * 4;
                    xbuf[(t0 + 0) * XST + ee] = v.x;
                    xbuf[(t0 + 1) * XST + ee] = v.y;
                    xbuf[(t0 + 2) * XST + ee] = v.z;
                    xbuf[(t0 + 3) * XST + ee] = v.w;
                }
            } else {
                const float xl = src[T_IN - 1];   // free-running: repeat last input
                #pragma unroll
                for (int k = 0; k < 16; k++)
                    xbuf[(half * 16 + k) * XST + ee] = xl;
            }
        }
        __syncthreads();

        #pragma unroll 1
        for (int i = 0; i < CHUNK; i++) {
            const float x = xbuf[i * XST + e];
            const ull xx = pk2(x, x);

            // ---------- layer 1 (2 owned units) ----------
            float hn[2];
            #pragma unroll
            for (int m = 0; m < 2; m++) {
                ull aif = ffma2(xx, wx_if[m], bz1_if[m]);
                ull ago = ffma2(xx, wx_go[m], bz1_go[m]);
                dot1(p1 + ((m * 2 + 0) * 6) * 6 + g, hh1, aif);
                dot1(p1 + ((m * 2 + 1) * 6) * 6 + g, hh1, ago);
                float2 gif = unpk(aif), ggo = unpk(ago);
                float cc = fmaf(sigf(gif.y), c1[m], sigf(gif.x) * tanh_fast(ggo.x));
                c1[m] = cc;
                hn[m] = sigf(ggo.y) * tanh_fast(cc);
            }
            {
                ulonglong2 v; v.x = pk2(hn[0], hn[0]); v.y = pk2(hn[1], hn[1]);
                *(ulonglong2*)&h1buf[e * HST + 2 * g] = v;
            }
            __syncthreads();
            #pragma unroll
            for (int jj = 0; jj < 6; jj++) {
                ulonglong2 v = *(const ulonglong2*)&h1buf[e * HST + 2 * jj];
                hh1[2 * jj] = v.x; hh1[2 * jj + 1] = v.y;
            }

            // ---------- layer 2 (split ih/hh accumulators: 12-deep chains) ----
            #pragma unroll
            for (int m = 0; m < 2; m++) {
                ull aif_i = bz2_if[m], ago_i = bz2_go[m];
                ull aif_h = 0ULL,      ago_h = 0ULL;
                dot1(pi2 + ((m * 2 + 0) * 6) * 6 + g, hh1, aif_i);
                dot1(pi2 + ((m * 2 + 1) * 6) * 6 + g, hh1, ago_i);
                dot1(ph2 + ((m * 2 + 0) * 6) * 6 + g, hh2, aif_h);
                dot1(ph2 + ((m * 2 + 1) * 6) * 6 + g, hh2, ago_h);
                float2 gif = unpk(add2(aif_i, aif_h));
                float2 ggo = unpk(add2(ago_i, ago_h));
                float cc = fmaf(sigf(gif.y), c2[m], sigf(gif.x) * tanh_fast(ggo.x));
                c2[m] = cc;
                hn[m] = sigf(ggo.y) * tanh_fast(cc);
            }
            {
                ulonglong2 v; v.x = pk2(hn[0], hn[0]); v.y = pk2(hn[1], hn[1]);
                *(ulonglong2*)&h2buf[e * HST + 2 * g] = v;
            }
            __syncthreads();
            #pragma unroll
            for (int jj = 0; jj < 6; jj++) {
                ulonglong2 v = *(const ulonglong2*)&h2buf[e * HST + 2 * jj];
                hh2[2 * jj] = v.x; hh2[2 * jj + 1] = v.y;
            }

            // ---------- linear head: warp 0 lanes 0..15 (one per element) ----
            if (tid < 16) {
                ull y = pk2(blin, blin);
                #pragma unroll
                for (int j = 0; j < 12; j++)
                    y = ffma2(hh2[j], s_wl[j], y);
                ybuf[i * XST + e] = unpk(y).x;
            }
        }
        __syncthreads();   // ybuf complete

        // ---- drain y chunk to gmem (float4 stores) ----
        if (tid < 32) {
            const int ee = tid & 15, half = tid >> 4;
            #pragma unroll
            for (int q = 0; q < 4; q++) {
                const int t0 = half * 16 + q * 4;
                float4 v;
                v.x = ybuf[(t0 + 0) * XST + ee];
                v.y = ybuf[(t0 + 1) * XST + ee];
                v.z = ybuf[(t0 + 2) * XST + ee];
                v.w = ybuf[(t0 + 3) * XST + ee];
                *(float4*)(out + (eg0 + ee) * T_OUT + tbase + t0) = v;
            }
        }
    }
}

extern "C" void kernel_launch(void* const* d_in, const int* in_sizes, int n_in,
                              void* d_out, int out_size) {
    // metadata order: input, future(int scalar), w_ih1, w_hh1, b_ih1, b_hh1,
    //                 w_ih2, w_hh2, b_ih2, b_hh2, w_lin, b_lin
    int base = (n_in >= 12 && in_sizes[1] == 1) ? 2 : 1;  // skip 'future' scalar if present
    const float* input = (const float*)d_in[0];
    const float* w_ih1 = (const float*)d_in[base + 0];
    const float* w_hh1 = (const float*)d_in[base + 1];
    const float* b_ih1 = (const float*)d_in[base + 2];
    const float* b_hh1 = (const float*)d_in[base + 3];
    const float* w_ih2 = (const float*)d_in[base + 4];
    const float* w_hh2 = (const float*)d_in[base + 5];
    const float* b_ih2 = (const float*)d_in[base + 6];
    const float* b_hh2 = (const float*)d_in[base + 7];
    const float* w_lin = (const float*)d_in[base + 8];
    const float* b_lin = (const float*)d_in[base + 9];

    lstm_seq_kernel<<<B_TOT / EPB, THREADS>>>(
        input, w_ih1, w_hh1, b_ih1, b_hh1,
        w_ih2, w_hh2, b_ih2, b_hh2, w_lin, b_lin,
        (float*)d_out);
}

// round 12
// speedup vs baseline: 1.3068x; 1.0822x over previous
#include <cuda_runtime.h>

#define B_TOT   8192
#define T_IN    1024
#define T_OUT   1088               // 1024 + 64 free-running
#define EPB     16                 // elements per block; lane pairs (e, e+8)
#define THREADS 96                 // thread: u = tid>>3 (unit 0..11), p = tid&7
#define CHUNK   32
#define NCHUNK  (T_OUT / CHUNK)    // 34
#define XSTF    17                 // xbuf/ybuf float row stride (odd)
#define HST     14                 // h buffers ull row stride (7 float4, odd -> conflict-free)

typedef unsigned long long ull;

__device__ __forceinline__ ull pk2(float lo, float hi) {
    ull r; asm("mov.b64 %0, {%1, %2};" : "=l"(r) : "f"(lo), "f"(hi)); return r;
}
__device__ __forceinline__ ull ffma2(ull a, ull b, ull c) {
    ull d; asm("fma.rn.f32x2 %0, %1, %2, %3;" : "=l"(d) : "l"(a), "l"(b), "l"(c)); return d;
}
__device__ __forceinline__ ull add2(ull a, ull b) {
    ull d; asm("add.rn.f32x2 %0, %1, %2;" : "=l"(d) : "l"(a), "l"(b)); return d;
}
__device__ __forceinline__ float2 unpk(ull v) {
    float lo, hi; asm("mov.b64 {%0, %1}, %2;" : "=f"(lo), "=f"(hi) : "l"(v));
    return make_float2(lo, hi);
}
__device__ __forceinline__ float tanh_fast(float x) {
    float y; asm("tanh.approx.f32 %0, %1;" : "=f"(y) : "f"(x)); return y;
}
__device__ __forceinline__ float sigf(float x) {
    return fmaf(tanh_fast(0.5f * x), 0.5f, 0.5f);
}

// pair-row dot for both elements; p pre-offset to this unit's slot, jj-stride
// = 12 ulonglong2 (unit-contiguous layout: warp's 4 units span 64B -> 1 wavefront)
__device__ __forceinline__ void dotu(const ulonglong2* __restrict__ p,
                                     const ull* ha, const ull* hb,
                                     ull& a0, ull& a1) {
    #pragma unroll
    for (int jj = 0; jj < 6; jj++) {
        ulonglong2 v = p[jj * 12];
        a0 = ffma2(ha[2 * jj],     v.x, a0);
        a0 = ffma2(ha[2 * jj + 1], v.y, a0);
        a1 = ffma2(hb[2 * jj],     v.x, a1);
        a1 = ffma2(hb[2 * jj + 1], v.y, a1);
    }
}

__global__ __launch_bounds__(THREADS, 4)
void lstm_seq_kernel(const float* __restrict__ input,
                     const float* __restrict__ w_ih1, const float* __restrict__ w_hh1,
                     const float* __restrict__ b_ih1, const float* __restrict__ b_hh1,
                     const float* __restrict__ w_ih2, const float* __restrict__ w_hh2,
                     const float* __restrict__ b_ih2, const float* __restrict__ b_hh2,
                     const float* __restrict__ w_lin, const float* __restrict__ b_lin,
                     float* __restrict__ out)
{
    // gate-packed, unit-contiguous weights: ull idx = ((q*6+jj)*12+u)*2+t,
    // j = 2jj+t; q=0 -> rows (u, 12+u) = (i,f); q=1 -> (24+u, 36+u) = (g,o)
    __shared__ alignas(16) ull s_w1[288], s_wi2[288], s_wh2[288];
    __shared__ alignas(16) ull s_wl[12];                 // pk2(wl_j, wl_j)
    __shared__ alignas(16) float xbuf[CHUNK * XSTF];
    __shared__ alignas(16) float ybuf[CHUNK * XSTF];
    __shared__ alignas(16) ull h1buf[2][EPB * HST];      // (h,h) packed, parity-buffered
    __shared__ alignas(16) ull h2buf[2][EPB * HST];

    const int tid = threadIdx.x;
    const int u   = tid >> 3;      // owned unit 0..11
    const int e0  = tid & 7;       // owned elements e0, e0+8
    const int e1  = e0 + 8;

    // ---- stage weights (idx decode is the identity: s[idx] = value(idx)) ----
    for (int idx = tid; idx < 288; idx += THREADS) {
        const int t  = idx & 1;
        const int r2 = idx >> 1;
        const int uu = r2 % 12;
        const int pos = r2 / 12;           // 0..11
        const int jj = pos % 6;
        const int q  = pos / 6;
        const int j  = 2 * jj + t;
        const int rA = (q ? 24 : 0) + uu;
        const int rB = (q ? 36 : 12) + uu;
        s_w1[idx]  = pk2(w_hh1[rA * 12 + j], w_hh1[rB * 12 + j]);
        s_wi2[idx] = pk2(w_ih2[rA * 12 + j], w_ih2[rB * 12 + j]);
        s_wh2[idx] = pk2(w_hh2[rA * 12 + j], w_hh2[rB * 12 + j]);
    }
    if (tid < 12) s_wl[tid] = pk2(w_lin[tid], w_lin[tid]);
    // zero both parities of h buffers (h1(-1)=0, h2(-1)=0 reads)
    for (int idx = tid; idx < 2 * EPB * HST; idx += THREADS) {
        ((ull*)h1buf)[idx] = 0ULL;
        ((ull*)h2buf)[idx] = 0ULL;
    }

    // per-thread packed constants for unit u
    const ull wx_if  = pk2(w_ih1[u],      w_ih1[12 + u]);
    const ull wx_go  = pk2(w_ih1[24 + u], w_ih1[36 + u]);
    const ull bz1_if = pk2(b_ih1[u] + b_hh1[u],           b_ih1[12 + u] + b_hh1[12 + u]);
    const ull bz1_go = pk2(b_ih1[24 + u] + b_hh1[24 + u], b_ih1[36 + u] + b_hh1[36 + u]);
    const ull bz2_if = pk2(b_ih2[u] + b_hh2[u],           b_ih2[12 + u] + b_hh2[12 + u]);
    const ull bz2_go = pk2(b_ih2[24 + u] + b_hh2[24 + u], b_ih2[36 + u] + b_hh2[36 + u]);
    const float blin = b_lin[0];

    float c1a = 0.0f, c1b = 0.0f, c2a = 0.0f, c2b = 0.0f;

    const size_t eg0 = (size_t)blockIdx.x * EPB;
    const ulonglong2* w1v  = (const ulonglong2*)s_w1;
    const ulonglong2* wi2v = (const ulonglong2*)s_wi2;
    const ulonglong2* wh2v = (const ulonglong2*)s_wh2;

    __syncthreads();

    for (int ck = 0; ck < NCHUNK; ck++) {
        const int tbase = ck * CHUNK;

        // ---- stage x chunk (tid<32: 2 threads per element, 16 steps each) ----
        if (tid < 32) {
            const int ee = tid & 15, half = tid >> 4;
            const float* src = input + (eg0 + ee) * T_IN;
            if (tbase < T_IN) {
                const float4* p = (const float4*)(src + tbase + half * 16);
                #pragma unroll
                for (int q = 0; q < 4; q++) {
                    float4 v = p[q];
                    const int t0 = half * 16 + q * 4;
                    xbuf[(t0 + 0) * XSTF + ee] = v.x;
                    xbuf[(t0 + 1) * XSTF + ee] = v.y;
                    xbuf[(t0 + 2) * XSTF + ee] = v.z;
                    xbuf[(t0 + 3) * XSTF + ee] = v.w;
                }
            } else {
                const float xl = src[T_IN - 1];   // free-running: repeat last input
                #pragma unroll
                for (int kk = 0; kk < 16; kk++)
                    xbuf[(half * 16 + kk) * XSTF + ee] = xl;
            }
        }
        __syncthreads();

        #pragma unroll 1
        for (int i = 0; i < CHUNK; i++) {
            const int k    = tbase + i;
            const int wsel = k & 1, rsel = wsel ^ 1;

            // ---- gather h1(k-1), h2(k-2) for both elements ----
            ull hh1a[12], hh1b[12], hh2a[12], hh2b[12];
            #pragma unroll
            for (int jj = 0; jj < 6; jj++) {
                ulonglong2 a = *(const ulonglong2*)&h1buf[rsel][e0 * HST + 2 * jj];
                hh1a[2 * jj] = a.x; hh1a[2 * jj + 1] = a.y;
                ulonglong2 b = *(const ulonglong2*)&h1buf[rsel][e1 * HST + 2 * jj];
                hh1b[2 * jj] = b.x; hh1b[2 * jj + 1] = b.y;
                ulonglong2 c = *(const ulonglong2*)&h2buf[rsel][e0 * HST + 2 * jj];
                hh2a[2 * jj] = c.x; hh2a[2 * jj + 1] = c.y;
                ulonglong2 d = *(const ulonglong2*)&h2buf[rsel][e1 * HST + 2 * jj];
                hh2b[2 * jj] = d.x; hh2b[2 * jj + 1] = d.y;
            }

            // ---- layer 1: h1(k) = f(x(k), h1(k-1)) ----
            {
                const float x0 = xbuf[i * XSTF + e0];
                const float x1 = xbuf[i * XSTF + e1];
                ull aif0 = ffma2(pk2(x0, x0), wx_if, bz1_if);
                ull ago0 = ffma2(pk2(x0, x0), wx_go, bz1_go);
                ull aif1 = ffma2(pk2(x1, x1), wx_if, bz1_if);
                ull ago1 = ffma2(pk2(x1, x1), wx_go, bz1_go);
                dotu(w1v + u,      hh1a, hh1b, aif0, aif1);
                dotu(w1v + 72 + u, hh1a, hh1b, ago0, ago1);
                {
                    float2 gif = unpk(aif0), ggo = unpk(ago0);
                    float cc = fmaf(sigf(gif.y), c1a, sigf(gif.x) * tanh_fast(ggo.x));
                    c1a = cc;
                    float hn = sigf(ggo.y) * tanh_fast(cc);
                    h1buf[wsel][e0 * HST + u] = pk2(hn, hn);
                }
                {
                    float2 gif = unpk(aif1), ggo = unpk(ago1);
                    float cc = fmaf(sigf(gif.y), c1b, sigf(gif.x) * tanh_fast(ggo.x));
                    c1b = cc;
                    float hn = sigf(ggo.y) * tanh_fast(cc);
                    h1buf[wsel][e1 * HST + u] = pk2(hn, hn);
                }
            }

            // ---- layer 2: h2(k-1) = g(h1(k-1), h2(k-2)) ----
            if (k >= 1) {
                ull bi0 = bz2_if, bg0 = bz2_go, bi1 = bz2_if, bg1 = bz2_go;
                ull ci0 = 0ULL, cg0 = 0ULL, ci1 = 0ULL, cg1 = 0ULL;
                dotu(wi2v + u,      hh1a, hh1b, bi0, bi1);
                dotu(wi2v + 72 + u, hh1a, hh1b, bg0, bg1);
                dotu(wh2v + u,      hh2a, hh2b, ci0, ci1);
                dotu(wh2v + 72 + u, hh2a, hh2b, cg0, cg1);
                {
                    float2 gif = unpk(add2(bi0, ci0)), ggo = unpk(add2(bg0, cg0));
                    float cc = fmaf(sigf(gif.y), c2a, sigf(gif.x) * tanh_fast(ggo.x));
                    c2a = cc;
                    float hn = sigf(ggo.y) * tanh_fast(cc);
                    h2buf[wsel][e0 * HST + u] = pk2(hn, hn);
                }
                {
                    float2 gif = unpk(add2(bi1, ci1)), ggo = unpk(add2(bg1, cg1));
                    float cc = fmaf(sigf(gif.y), c2b, sigf(gif.x) * tanh_fast(ggo.x));
                    c2b = cc;
                    float hn = sigf(ggo.y) * tanh_fast(cc);
                    h2buf[wsel][e1 * HST + u] = pk2(hn, hn);
                }
            }

            // ---- head: y(k-2) from the gathered h2(k-2) ----
            if (u == 0 && k >= 2) {
                ull y0 = pk2(blin, blin), y1 = y0;
                #pragma unroll
                for (int j = 0; j < 12; j++) {
                    y0 = ffma2(hh2a[j], s_wl[j], y0);
                    y1 = ffma2(hh2b[j], s_wl[j], y1);
                }
                ybuf[i * XSTF + e0] = unpk(y0).x;
                ybuf[i * XSTF + e1] = unpk(y1).x;
            }
            __syncthreads();   // the ONLY per-step barrier
        }

        // ---- drain ybuf: slot j holds y(tbase-2+j) ----
        if (tid < 32) {
            const int ee = tid & 15, half = tid >> 4;
            #pragma unroll
            for (int q = 0; q < 8; q++) {
                const int j = half * 16 + q * 2;
                const int t = tbase - 2 + j;
                if (t >= 0) {
                    float2 v = make_float2(ybuf[j * XSTF + ee], ybuf[(j + 1) * XSTF + ee]);
                    *(float2*)(out + (eg0 + ee) * T_OUT + t) = v;
                }
            }
        }
    }

    // ---- epilogue: y(1086) and final h2(1087) -> y(1087) ----
    {
        ull hh1a[12], hh1b[12], hh2a[12], hh2b[12];
        #pragma unroll
        for (int jj = 0; jj < 6; jj++) {
            ulonglong2 a = *(const ulonglong2*)&h1buf[1][e0 * HST + 2 * jj];
            hh1a[2 * jj] = a.x; hh1a[2 * jj + 1] = a.y;
            ulonglong2 b = *(const ulonglong2*)&h1buf[1][e1 * HST + 2 * jj];
            hh1b[2 * jj] = b.x; hh1b[2 * jj + 1] = b.y;
            ulonglong2 c = *(const ulonglong2*)&h2buf[1][e0 * HST + 2 * jj];
            hh2a[2 * jj] = c.x; hh2a[2 * jj + 1] = c.y;
            ulonglong2 d = *(const ulonglong2*)&h2buf[1][e1 * HST + 2 * jj];
            hh2b[2 * jj] = d.x; hh2b[2 * jj + 1] = d.y;
        }
        if (u == 0) {   // y(1086) from h2(1086)
            ull y0 = pk2(blin, blin), y1 = y0;
            #pragma unroll
            for (int j = 0; j < 12; j++) {
                y0 = ffma2(hh2a[j], s_wl[j], y0);
                y1 = ffma2(hh2b[j], s_wl[j], y1);
            }
            out[(eg0 + e0) * T_OUT + (T_OUT - 2)] = unpk(y0).x;
            out[(eg0 + e1) * T_OUT + (T_OUT - 2)] = unpk(y1).x;
        }
        // h2(1087) = g(h1(1087), h2(1086))
        ull bi0 = bz2_if, bg0 = bz2_go, bi1 = bz2_if, bg1 = bz2_go;
        ull ci0 = 0ULL, cg0 = 0ULL, ci1 = 0ULL, cg1 = 0ULL;
        dotu(wi2v + u,      hh1a, hh1b, bi0, bi1);
        dotu(wi2v + 72 + u, hh1a, hh1b, bg0, bg1);
        dotu(wh2v + u,      hh2a, hh2b, ci0, ci1);
        dotu(wh2v + 72 + u, hh2a, hh2b, cg0, cg1);
        {
            float2 gif = unpk(add2(bi0, ci0)), ggo = unpk(add2(bg0, cg0));
            float cc = fmaf(sigf(gif.y), c2a, sigf(gif.x) * tanh_fast(ggo.x));
            float hn = sigf(ggo.y) * tanh_fast(cc);
            h2buf[0][e0 * HST + u] = pk2(hn, hn);
        }
        {
            float2 gif = unpk(add2(bi1, ci1)), ggo = unpk(add2(bg1, cg1));
            float cc = fmaf(sigf(gif.y), c2b, sigf(gif.x) * tanh_fast(ggo.x));
            float hn = sigf(ggo.y) * tanh_fast(cc);
            h2buf[0][e1 * HST + u] = pk2(hn, hn);
        }
        __syncthreads();
        if (u == 0) {   // y(1087)
            ull y0 = pk2(blin, blin), y1 = y0;
            #pragma unroll
            for (int j = 0; j < 6; j++) {
                ulonglong2 a = *(const ulonglong2*)&h2buf[0][e0 * HST + 2 * j];
                ulonglong2 b = *(const ulonglong2*)&h2buf[0][e1 * HST + 2 * j];
                y0 = ffma2(a.x, s_wl[2 * j], y0);
                y0 = ffma2(a.y, s_wl[2 * j + 1], y0);
                y1 = ffma2(b.x, s_wl[2 * j], y1);
                y1 = ffma2(b.y, s_wl[2 * j + 1], y1);
            }
            out[(eg0 + e0) * T_OUT + (T_OUT - 1)] = unpk(y0).x;
            out[(eg0 + e1) * T_OUT + (T_OUT - 1)] = unpk(y1).x;
        }
    }
}

extern "C" void kernel_launch(void* const* d_in, const int* in_sizes, int n_in,
                              void* d_out, int out_size) {
    // metadata order: input, future(int scalar), w_ih1, w_hh1, b_ih1, b_hh1,
    //                 w_ih2, w_hh2, b_ih2, b_hh2, w_lin, b_lin
    int base = (n_in >= 12 && in_sizes[1] == 1) ? 2 : 1;  // skip 'future' scalar if present
    const float* input = (const float*)d_in[0];
    const float* w_ih1 = (const float*)d_in[base + 0];
    const float* w_hh1 = (const float*)d_in[base + 1];
    const float* b_ih1 = (const float*)d_in[base + 2];
    const float* b_hh1 = (const float*)d_in[base + 3];
    const float* w_ih2 = (const float*)d_in[base + 4];
    const float* w_hh2 = (const float*)d_in[base + 5];
    const float* b_ih2 = (const float*)d_in[base + 6];
    const float* b_hh2 = (const float*)d_in[base + 7];
    const float* w_lin = (const float*)d_in[base + 8];
    const float* b_lin = (const float*)d_in[base + 9];

    lstm_seq_kernel<<<B_TOT / EPB, THREADS>>>(
        input, w_ih1, w_hh1, b_ih1, b_hh1,
        w_ih2, w_hh2, b_ih2, b_hh2, w_lin, b_lin,
        (float*)d_out);
}